// round 1
// baseline (speedup 1.0000x reference)
#include <cuda_runtime.h>
#include <cuda_bf16.h>
#include <cstdint>
#include <cstddef>

// ============================================================================
// Attention_5480378270188 — bf16x2 (hi/lo split) mma.sync baseline
//   out = softmax(mask(Q Wq^T (K Wk^T)^T)) (V Wv^T)
// B=8, N=M=2048, D_MODEL=D_K=D_V=1024
// 4 stages: proj GEMMs -> score GEMM(+mask) -> softmax -> out GEMM
// All GEMMs use 3-term bf16 split (hi*hi + hi*lo + lo*hi) for ~fp32 accuracy.
// ============================================================================

#define DEV_INLINE __device__ __forceinline__

constexpr int BB = 8;
constexpr int NN = 2048;
constexpr int MM = 2048;
constexpr int DD = 1024;
constexpr float NEG = -1000000000.0f;

constexpr size_t QKV_ELEMS = (size_t)BB * NN * DD;   // 16,777,216
constexpr size_t SCORE_ELEMS = (size_t)BB * NN * MM; // 33,554,432

// Scratch (device globals; no allocation in kernel_launch)
__device__ __nv_bfloat16 g_qhi[QKV_ELEMS];
__device__ __nv_bfloat16 g_qlo[QKV_ELEMS];
__device__ __nv_bfloat16 g_khi[QKV_ELEMS];
__device__ __nv_bfloat16 g_klo[QKV_ELEMS];
__device__ __nv_bfloat16 g_vhi[QKV_ELEMS];
__device__ __nv_bfloat16 g_vlo[QKV_ELEMS];
__device__ float         g_scores[SCORE_ELEMS];
__device__ __nv_bfloat16 g_whi[SCORE_ELEMS];
__device__ __nv_bfloat16 g_wlo[SCORE_ELEMS];

// smem strides (bf16 elements), padded for bank-conflict mitigation
#define LDA  40    // 128 x (32+8)
#define LDBT 136   // 32 x (128+8) for transposed-B (v) tiles

// ---------------------------------------------------------------------------
// PTX helpers
// ---------------------------------------------------------------------------
DEV_INLINE uint32_t smem_u32(const void* p) {
    return (uint32_t)__cvta_generic_to_shared(p);
}

DEV_INLINE void ldsm4(uint32_t r[4], const void* p) {
    uint32_t a = smem_u32(p);
    asm volatile("ldmatrix.sync.aligned.m8n8.x4.shared.b16 {%0,%1,%2,%3}, [%4];\n"
                 : "=r"(r[0]), "=r"(r[1]), "=r"(r[2]), "=r"(r[3]) : "r"(a));
}

DEV_INLINE void ldsm4t(uint32_t r[4], const void* p) {
    uint32_t a = smem_u32(p);
    asm volatile("ldmatrix.sync.aligned.m8n8.x4.trans.shared.b16 {%0,%1,%2,%3}, [%4];\n"
                 : "=r"(r[0]), "=r"(r[1]), "=r"(r[2]), "=r"(r[3]) : "r"(a));
}

DEV_INLINE void mma16816(float c[4], const uint32_t a[4], uint32_t b0, uint32_t b1) {
    asm volatile(
        "mma.sync.aligned.m16n8k16.row.col.f32.bf16.bf16.f32 "
        "{%0,%1,%2,%3},{%4,%5,%6,%7},{%8,%9},{%0,%1,%2,%3};\n"
        : "+f"(c[0]), "+f"(c[1]), "+f"(c[2]), "+f"(c[3])
        : "r"(a[0]), "r"(a[1]), "r"(a[2]), "r"(a[3]), "r"(b0), "r"(b1));
}

DEV_INLINE void split1(float v, __nv_bfloat16& h, __nv_bfloat16& l) {
    h = __float2bfloat16(v);
    l = __float2bfloat16(v - __bfloat162float(h));
}

// split a float4 into hi/lo bf16 pairs, store (o must be 4-elem aligned)
DEV_INLINE void split4_store(float4 v, __nv_bfloat16* ph, __nv_bfloat16* pl, int o) {
    __nv_bfloat16 h0, l0, h1, l1, h2, l2, h3, l3;
    split1(v.x, h0, l0); split1(v.y, h1, l1);
    split1(v.z, h2, l2); split1(v.w, h3, l3);
    *(__nv_bfloat162*)(ph + o)     = __halves2bfloat162(h0, h1);
    *(__nv_bfloat162*)(ph + o + 2) = __halves2bfloat162(h2, h3);
    *(__nv_bfloat162*)(pl + o)     = __halves2bfloat162(l0, l1);
    *(__nv_bfloat162*)(pl + o + 2) = __halves2bfloat162(l2, l3);
}

// ---------------------------------------------------------------------------
// Compute core: one 32-wide K-chunk. CTA tile 128x128, 8 warps (4m x 2n),
// warp tile 32(m) x 64(n). acc[2][8][4] fp32. 3-term bf16x2.
// ---------------------------------------------------------------------------
DEV_INLINE void compute_chunk_nt(const __nv_bfloat16* sAh, const __nv_bfloat16* sAl,
                                 const __nv_bfloat16* sBh, const __nv_bfloat16* sBl,
                                 int wm, int wn, int lane, float (&acc)[2][8][4]) {
#pragma unroll
    for (int kk = 0; kk < 32; kk += 16) {
        uint32_t ah[2][4], al[2][4], bh[4][4], bl[4][4];
#pragma unroll
        for (int mt = 0; mt < 2; mt++) {
            int r = wm + mt * 16 + (lane & 15);
            int c = kk + (lane >> 4) * 8;
            ldsm4(ah[mt], sAh + r * LDA + c);
            ldsm4(al[mt], sAl + r * LDA + c);
        }
#pragma unroll
        for (int p = 0; p < 4; p++) {
            int r = wn + p * 16 + (lane >> 4) * 8 + (lane & 7);
            int c = kk + ((lane >> 3) & 1) * 8;
            ldsm4(bh[p], sBh + r * LDA + c);
            ldsm4(bl[p], sBl + r * LDA + c);
        }
#pragma unroll
        for (int mt = 0; mt < 2; mt++)
#pragma unroll
            for (int p = 0; p < 4; p++) {
                mma16816(acc[mt][2 * p],     ah[mt], bh[p][0], bh[p][1]);
                mma16816(acc[mt][2 * p],     ah[mt], bl[p][0], bl[p][1]);
                mma16816(acc[mt][2 * p],     al[mt], bh[p][0], bh[p][1]);
                mma16816(acc[mt][2 * p + 1], ah[mt], bh[p][2], bh[p][3]);
                mma16816(acc[mt][2 * p + 1], ah[mt], bl[p][2], bl[p][3]);
                mma16816(acc[mt][2 * p + 1], al[mt], bh[p][2], bh[p][3]);
            }
    }
}

// Same, but B stored [k=32][n=128+pad] (row-major K) -> ldmatrix.trans
DEV_INLINE void compute_chunk_t(const __nv_bfloat16* sAh, const __nv_bfloat16* sAl,
                                const __nv_bfloat16* sBh, const __nv_bfloat16* sBl,
                                int wm, int wn, int lane, float (&acc)[2][8][4]) {
#pragma unroll
    for (int kk = 0; kk < 32; kk += 16) {
        uint32_t ah[2][4], al[2][4], bh[4][4], bl[4][4];
#pragma unroll
        for (int mt = 0; mt < 2; mt++) {
            int r = wm + mt * 16 + (lane & 15);
            int c = kk + (lane >> 4) * 8;
            ldsm4(ah[mt], sAh + r * LDA + c);
            ldsm4(al[mt], sAl + r * LDA + c);
        }
#pragma unroll
        for (int p = 0; p < 4; p++) {
            int r = kk + ((lane >> 3) & 1) * 8 + (lane & 7);
            int c = wn + p * 16 + (lane >> 4) * 8;
            ldsm4t(bh[p], sBh + r * LDBT + c);
            ldsm4t(bl[p], sBl + r * LDBT + c);
        }
#pragma unroll
        for (int mt = 0; mt < 2; mt++)
#pragma unroll
            for (int p = 0; p < 4; p++) {
                mma16816(acc[mt][2 * p],     ah[mt], bh[p][0], bh[p][1]);
                mma16816(acc[mt][2 * p],     ah[mt], bl[p][0], bl[p][1]);
                mma16816(acc[mt][2 * p],     al[mt], bh[p][0], bh[p][1]);
                mma16816(acc[mt][2 * p + 1], ah[mt], bh[p][2], bh[p][3]);
                mma16816(acc[mt][2 * p + 1], ah[mt], bl[p][2], bl[p][3]);
                mma16816(acc[mt][2 * p + 1], al[mt], bh[p][2], bh[p][3]);
            }
    }
}

// ---------------------------------------------------------------------------
// Kernel 1: projection  C[r,o] = sum_d X[r,d]*W[o,d] + b[o]
// X: [16384,1024] fp32 (batch fused), W: [1024,1024] fp32. Out: bf16 hi/lo.
// grid (8 colTiles, 128 rowTiles), 256 threads.
// ---------------------------------------------------------------------------
template <int WHICH>
__global__ __launch_bounds__(256, 1) void proj_kernel(const float* __restrict__ X,
                                                      const float* __restrict__ W,
                                                      const float* __restrict__ bias) {
    __shared__ __align__(16) __nv_bfloat16 sAh[128 * LDA], sAl[128 * LDA];
    __shared__ __align__(16) __nv_bfloat16 sBh[128 * LDA], sBl[128 * LDA];
    const int tid = threadIdx.x, lane = tid & 31, warp = tid >> 5;
    const int wm = (warp & 3) * 32, wn = (warp >> 2) * 64;
    const int rowBlk = blockIdx.y * 128, colBlk = blockIdx.x * 128;
    const int lrow = tid >> 1, lcol = (tid & 1) * 16;
    const float* Ag = X + (size_t)(rowBlk + lrow) * DD + lcol;
    const float* Bg = W + (size_t)(colBlk + lrow) * DD + lcol;

    float acc[2][8][4] = {};
    for (int k0 = 0; k0 < DD; k0 += 32) {
        const int o = lrow * LDA + lcol;
#pragma unroll
        for (int i = 0; i < 4; i++) {
            float4 a = *(const float4*)(Ag + k0 + i * 4);
            float4 b = *(const float4*)(Bg + k0 + i * 4);
            split4_store(a, sAh, sAl, o + i * 4);
            split4_store(b, sBh, sBl, o + i * 4);
        }
        __syncthreads();
        compute_chunk_nt(sAh, sAl, sBh, sBl, wm, wn, lane, acc);
        __syncthreads();
    }

    __nv_bfloat16 *Chi, *Clo;
    if (WHICH == 0)      { Chi = g_qhi; Clo = g_qlo; }
    else if (WHICH == 1) { Chi = g_khi; Clo = g_klo; }
    else                 { Chi = g_vhi; Clo = g_vlo; }

#pragma unroll
    for (int mt = 0; mt < 2; mt++)
#pragma unroll
        for (int nt = 0; nt < 8; nt++) {
            int r = rowBlk + wm + mt * 16 + (lane >> 2);
            int c = colBlk + wn + nt * 8 + (lane & 3) * 2;
            float b0 = bias[c], b1 = bias[c + 1];
            {
                __nv_bfloat16 h0, l0, h1, l1;
                split1(acc[mt][nt][0] + b0, h0, l0);
                split1(acc[mt][nt][1] + b1, h1, l1);
                *(__nv_bfloat162*)(Chi + (size_t)r * DD + c) = __halves2bfloat162(h0, h1);
                *(__nv_bfloat162*)(Clo + (size_t)r * DD + c) = __halves2bfloat162(l0, l1);
            }
            {
                __nv_bfloat16 h0, l0, h1, l1;
                split1(acc[mt][nt][2] + b0, h0, l0);
                split1(acc[mt][nt][3] + b1, h1, l1);
                *(__nv_bfloat162*)(Chi + (size_t)(r + 8) * DD + c) = __halves2bfloat162(h0, h1);
                *(__nv_bfloat162*)(Clo + (size_t)(r + 8) * DD + c) = __halves2bfloat162(l0, l1);
            }
        }
}

// ---------------------------------------------------------------------------
// Kernel 2: scores S[b,n,m] = sum_d q[b,n,d]*k[b,m,d], masked.
// grid (16 mTiles, 16 nTiles, 8 batch).
// ---------------------------------------------------------------------------
__global__ __launch_bounds__(256, 1) void score_kernel(const int* __restrict__ mask) {
    __shared__ __align__(16) __nv_bfloat16 sAh[128 * LDA], sAl[128 * LDA];
    __shared__ __align__(16) __nv_bfloat16 sBh[128 * LDA], sBl[128 * LDA];
    const int tid = threadIdx.x, lane = tid & 31, warp = tid >> 5;
    const int wm = (warp & 3) * 32, wn = (warp >> 2) * 64;
    const int b = blockIdx.z;
    const int rowBlk = blockIdx.y * 128, colBlk = blockIdx.x * 128;
    const size_t qoff = (size_t)b * NN * DD;
    const int lrow = tid >> 1, lcol = (tid & 1) * 16;

    const __nv_bfloat16* pqh = g_qhi + qoff + (size_t)(rowBlk + lrow) * DD + lcol;
    const __nv_bfloat16* pql = g_qlo + qoff + (size_t)(rowBlk + lrow) * DD + lcol;
    const __nv_bfloat16* pkh = g_khi + qoff + (size_t)(colBlk + lrow) * DD + lcol;
    const __nv_bfloat16* pkl = g_klo + qoff + (size_t)(colBlk + lrow) * DD + lcol;

    float acc[2][8][4] = {};
    for (int k0 = 0; k0 < DD; k0 += 32) {
        const int o = lrow * LDA + lcol;
        *(uint4*)(sAh + o)     = *(const uint4*)(pqh + k0);
        *(uint4*)(sAh + o + 8) = *(const uint4*)(pqh + k0 + 8);
        *(uint4*)(sAl + o)     = *(const uint4*)(pql + k0);
        *(uint4*)(sAl + o + 8) = *(const uint4*)(pql + k0 + 8);
        *(uint4*)(sBh + o)     = *(const uint4*)(pkh + k0);
        *(uint4*)(sBh + o + 8) = *(const uint4*)(pkh + k0 + 8);
        *(uint4*)(sBl + o)     = *(const uint4*)(pkl + k0);
        *(uint4*)(sBl + o + 8) = *(const uint4*)(pkl + k0 + 8);
        __syncthreads();
        compute_chunk_nt(sAh, sAl, sBh, sBl, wm, wn, lane, acc);
        __syncthreads();
    }

    float* Sg = g_scores + (size_t)b * NN * MM;
#pragma unroll
    for (int mt = 0; mt < 2; mt++)
#pragma unroll
        for (int nt = 0; nt < 8; nt++) {
            int r = rowBlk + wm + mt * 16 + (lane >> 2);
            int c = colBlk + wn + nt * 8 + (lane & 3) * 2;
            {
                int m0 = mask[(size_t)r * MM + c], m1 = mask[(size_t)r * MM + c + 1];
                float2 v;
                v.x = m0 ? acc[mt][nt][0] : NEG;
                v.y = m1 ? acc[mt][nt][1] : NEG;
                *(float2*)(Sg + (size_t)r * MM + c) = v;
            }
            {
                int rr = r + 8;
                int m0 = mask[(size_t)rr * MM + c], m1 = mask[(size_t)rr * MM + c + 1];
                float2 v;
                v.x = m0 ? acc[mt][nt][2] : NEG;
                v.y = m1 ? acc[mt][nt][3] : NEG;
                *(float2*)(Sg + (size_t)rr * MM + c) = v;
            }
        }
}

// ---------------------------------------------------------------------------
// Kernel 3: row softmax -> weights bf16 hi/lo. One CTA (256 thr) per row.
// ---------------------------------------------------------------------------
__global__ __launch_bounds__(256, 1) void softmax_kernel() {
    const int row = blockIdx.x;
    const int tid = threadIdx.x, lane = tid & 31, warp = tid >> 5;
    const float4* S4 = (const float4*)(g_scores + (size_t)row * MM);
    float4 u0 = S4[tid * 2], u1 = S4[tid * 2 + 1];
    float x[8] = {u0.x, u0.y, u0.z, u0.w, u1.x, u1.y, u1.z, u1.w};

    float mx = x[0];
#pragma unroll
    for (int i = 1; i < 8; i++) mx = fmaxf(mx, x[i]);
#pragma unroll
    for (int o = 16; o; o >>= 1) mx = fmaxf(mx, __shfl_xor_sync(0xffffffffu, mx, o));
    __shared__ float redm[8], reds[8];
    if (lane == 0) redm[warp] = mx;
    __syncthreads();
    mx = redm[0];
#pragma unroll
    for (int i = 1; i < 8; i++) mx = fmaxf(mx, redm[i]);

    float e[8], s = 0.f;
#pragma unroll
    for (int i = 0; i < 8; i++) { e[i] = __expf(x[i] - mx); s += e[i]; }
#pragma unroll
    for (int o = 16; o; o >>= 1) s += __shfl_xor_sync(0xffffffffu, s, o);
    if (lane == 0) reds[warp] = s;
    __syncthreads();
    s = reds[0];
#pragma unroll
    for (int i = 1; i < 8; i++) s += reds[i];
    float inv = 1.0f / s;

    __nv_bfloat16 h[8], l[8];
#pragma unroll
    for (int i = 0; i < 8; i++) split1(e[i] * inv, h[i], l[i]);
    uint4 uh, ul;
    __nv_bfloat162* ph = reinterpret_cast<__nv_bfloat162*>(&uh);
    __nv_bfloat162* pl = reinterpret_cast<__nv_bfloat162*>(&ul);
    ph[0] = __halves2bfloat162(h[0], h[1]); ph[1] = __halves2bfloat162(h[2], h[3]);
    ph[2] = __halves2bfloat162(h[4], h[5]); ph[3] = __halves2bfloat162(h[6], h[7]);
    pl[0] = __halves2bfloat162(l[0], l[1]); pl[1] = __halves2bfloat162(l[2], l[3]);
    pl[2] = __halves2bfloat162(l[4], l[5]); pl[3] = __halves2bfloat162(l[6], l[7]);
    *(uint4*)(g_whi + (size_t)row * MM + tid * 8) = uh;
    *(uint4*)(g_wlo + (size_t)row * MM + tid * 8) = ul;
}

// ---------------------------------------------------------------------------
// Kernel 4: out O[b,n,d] = sum_m w[b,n,m] * v[b,m,d]. B is K-major -> trans.
// grid (8 dTiles, 16 nTiles, 8 batch).
// ---------------------------------------------------------------------------
__global__ __launch_bounds__(256, 1) void out_kernel(float* __restrict__ O) {
    __shared__ __align__(16) __nv_bfloat16 sAh[128 * LDA], sAl[128 * LDA];
    __shared__ __align__(16) __nv_bfloat16 sBh[32 * LDBT], sBl[32 * LDBT];
    const int tid = threadIdx.x, lane = tid & 31, warp = tid >> 5;
    const int wm = (warp & 3) * 32, wn = (warp >> 2) * 64;
    const int b = blockIdx.z;
    const int rowBlk = blockIdx.y * 128, colBlk = blockIdx.x * 128;
    const size_t woff = (size_t)b * NN * MM;
    const size_t voff = (size_t)b * MM * DD;

    const int lrowA = tid >> 1, lcolA = (tid & 1) * 16;
    const __nv_bfloat16* pwh = g_whi + woff + (size_t)(rowBlk + lrowA) * MM + lcolA;
    const __nv_bfloat16* pwl = g_wlo + woff + (size_t)(rowBlk + lrowA) * MM + lcolA;
    const int lrowB = tid >> 3, lcolB = (tid & 7) * 16;
    const __nv_bfloat16* pvh = g_vhi + voff + (size_t)lrowB * DD + colBlk + lcolB;
    const __nv_bfloat16* pvl = g_vlo + voff + (size_t)lrowB * DD + colBlk + lcolB;

    float acc[2][8][4] = {};
    for (int k0 = 0; k0 < MM; k0 += 32) {
        const int oA = lrowA * LDA + lcolA;
        *(uint4*)(sAh + oA)     = *(const uint4*)(pwh + k0);
        *(uint4*)(sAh + oA + 8) = *(const uint4*)(pwh + k0 + 8);
        *(uint4*)(sAl + oA)     = *(const uint4*)(pwl + k0);
        *(uint4*)(sAl + oA + 8) = *(const uint4*)(pwl + k0 + 8);
        const int oB = lrowB * LDBT + lcolB;
        const size_t gvo = (size_t)k0 * DD;
        *(uint4*)(sBh + oB)     = *(const uint4*)(pvh + gvo);
        *(uint4*)(sBh + oB + 8) = *(const uint4*)(pvh + gvo + 8);
        *(uint4*)(sBl + oB)     = *(const uint4*)(pvl + gvo);
        *(uint4*)(sBl + oB + 8) = *(const uint4*)(pvl + gvo + 8);
        __syncthreads();
        compute_chunk_t(sAh, sAl, sBh, sBl, wm, wn, lane, acc);
        __syncthreads();
    }

    float* Og = O + (size_t)b * NN * DD;
#pragma unroll
    for (int mt = 0; mt < 2; mt++)
#pragma unroll
        for (int nt = 0; nt < 8; nt++) {
            int r = rowBlk + wm + mt * 16 + (lane >> 2);
            int c = colBlk + wn + nt * 8 + (lane & 3) * 2;
            float2 v0; v0.x = acc[mt][nt][0]; v0.y = acc[mt][nt][1];
            *(float2*)(Og + (size_t)r * DD + c) = v0;
            float2 v1; v1.x = acc[mt][nt][2]; v1.y = acc[mt][nt][3];
            *(float2*)(Og + (size_t)(r + 8) * DD + c) = v1;
        }
}

// ---------------------------------------------------------------------------
// Launch
// ---------------------------------------------------------------------------
extern "C" void kernel_launch(void* const* d_in, const int* in_sizes, int n_in,
                              void* d_out, int out_size) {
    (void)in_sizes; (void)n_in; (void)out_size;
    const float* querys = (const float*)d_in[0];
    const float* keys   = (const float*)d_in[1];
    const float* values = (const float*)d_in[2];
    const int*   mask   = (const int*)d_in[3];
    const float* Wq     = (const float*)d_in[4];
    const float* bq     = (const float*)d_in[5];
    const float* Wk     = (const float*)d_in[6];
    const float* bk     = (const float*)d_in[7];
    const float* Wv     = (const float*)d_in[8];
    const float* bv     = (const float*)d_in[9];
    float* out = (float*)d_out;

    dim3 blk(256);
    proj_kernel<0><<<dim3(8, 128), blk>>>(querys, Wq, bq);
    proj_kernel<1><<<dim3(8, 128), blk>>>(keys,   Wk, bk);
    proj_kernel<2><<<dim3(8, 128), blk>>>(values, Wv, bv);
    score_kernel<<<dim3(16, 16, 8), blk>>>(mask);
    softmax_kernel<<<dim3(16384), blk>>>();
    out_kernel<<<dim3(8, 16, 8), blk>>>(out);
}